// round 16
// baseline (speedup 1.0000x reference)
#include <cuda_runtime.h>
#include <cuda_bf16.h>
#include <math.h>
#include <stdint.h>

#define B_  128
#define S_  128
#define W_  16
#define V_  128
#define H_  512
#define G3_ 1536
#define L_  64

// k_step smem layout
#define WPSZ  49920                    // 48 rows x 1040B per precision
#define OFF_W 0                        // 2 prec -> 99840
#define ASZ   17408                    // 64 rows x 272B
#define OFF_A 99840                    // [buf][prec] x 17408 -> 69632
#define OFF_C 169472                   // 48 x 68 fp32 = 13056
#define STEP_SMEM 182528

// k_xws smem layout (g-tile 64, dual-g threads)
#define XT_G  64
#define XS_WS 0                        // 128 v x 66 fp32 = 33792
#define XS_OS 33792                    // 128 b x 66 fp32 = 33792
#define XS_CS 67584                    // 128 b x 16 int  = 8192
#define XS_FS 75776                    // 128 b x 16 fp32 = 8192
#define XS_SMEM 83968

// k_lin_mma smem layout
#define LASZ  17408                    // 64 rows x 272B
#define LOFF_A 0                       // [buf2][prec2] -> 69632
#define LOFF_B 69632                   // [buf2][prec2] -> 69632
#define LOFF_C 139264                  // 64 x 68 fp32 = 17408
#define LIN_SMEM 156672

// ---------------- scratch (device globals; no allocation) ----------------
__device__ float g_wt [B_*S_*W_];
__device__ float g_xw [(size_t)2*S_*G3_*B_];          // [dir][t][g][b] incl b_ih
__device__ __nv_bfloat16 g_hbf[2][2][2][B_][H_];      // [parity][dir][prec][b][k]
__device__ __nv_bfloat16 g_wp [2][2][G3_][H_];        // [prec][dir][perm row][k]
__device__ __nv_bfloat16 g_gb [2][2][S_][B_][H_];     // [prec][dir][t][b][u] masked out
__device__ __nv_bfloat16 g_wlb[2][L_][2*H_];          // [prec][l][k] W_lin split
__device__ float g_zbuf[64];                          // stays zero (never written)
__device__ int   g_bar4[4];

// ---------------- helpers ----------------
__device__ __forceinline__ uint32_t s2u(const void* p){
    uint32_t a;
    asm("{ .reg .u64 t; cvta.to.shared.u64 t, %1; cvt.u32.u64 %0, t; }" : "=r"(a) : "l"(p));
    return a;
}
__device__ __forceinline__ void ldsm4(uint32_t* r, uint32_t a){
    asm volatile("ldmatrix.sync.aligned.m8n8.x4.shared.b16 {%0,%1,%2,%3}, [%4];"
        : "=r"(r[0]), "=r"(r[1]), "=r"(r[2]), "=r"(r[3]) : "r"(a));
}
__device__ __forceinline__ void ldsm2(uint32_t* r, uint32_t a){
    asm volatile("ldmatrix.sync.aligned.m8n8.x2.shared.b16 {%0,%1}, [%2];"
        : "=r"(r[0]), "=r"(r[1]) : "r"(a));
}
__device__ __forceinline__ void mma16816(float* c, const uint32_t* a, const uint32_t* b){
    asm volatile("mma.sync.aligned.m16n8k16.row.col.f32.bf16.bf16.f32 "
        "{%0,%1,%2,%3}, {%4,%5,%6,%7}, {%8,%9}, {%0,%1,%2,%3};"
        : "+f"(c[0]), "+f"(c[1]), "+f"(c[2]), "+f"(c[3])
        : "r"(a[0]), "r"(a[1]), "r"(a[2]), "r"(a[3]), "r"(b[0]), "r"(b[1]));
}
__device__ __forceinline__ void cpa16(uint32_t dst, const void* src){
    asm volatile("cp.async.cg.shared.global [%0], [%1], 16;" :: "r"(dst), "l"(src));
}
__device__ __forceinline__ float fsig(float x){
    return __fdividef(1.f, 1.f + __expf(-x));
}
__device__ __forceinline__ float ftanh(float x){
    float e = __expf(2.f*fabsf(x));
    return copysignf(1.f - __fdividef(2.f, e + 1.f), x);
}

// ---------------- init (re-run every replay) ----------------
__global__ void k_zero(){
    int i = blockIdx.x * 256 + threadIdx.x;
    if (i < 4*B_*H_) ((uint32_t*)g_hbf)[i] = 0u;
    if (i < 4) g_bar4[i] = 0;
}

// ---------------- permute + split W_hh into bf16 hi/lo --------------------
__global__ void k_prep(const float* __restrict__ Wf, const float* __restrict__ Wb){
    int e = blockIdx.x * 256 + threadIdx.x;
    if (e >= 2*G3_*H_) return;
    int dir = e / (G3_*H_);
    int rem = e - dir*(G3_*H_);
    int ro  = rem / H_;
    int k   = rem % H_;
    int u = ro / 3, g = ro % 3;
    float w = (dir ? Wb : Wf)[(g*H_ + u)*H_ + k];
    __nv_bfloat16 hi = __float2bfloat16(w);
    __nv_bfloat16 lo = __float2bfloat16(w - __bfloat162float(hi));
    g_wp[0][dir][ro][k] = hi;
    g_wp[1][dir][ro][k] = lo;
}

// ---------------- split W_lin into bf16 hi/lo ----------------
__global__ void k_prepL(const float* __restrict__ Wlin){
    int e = blockIdx.x * 256 + threadIdx.x;
    if (e >= L_*2*H_) return;
    float w = Wlin[e];
    __nv_bfloat16 hi = __float2bfloat16(w);
    __nv_bfloat16 lo = __float2bfloat16(w - __bfloat162float(hi));
    ((__nv_bfloat16*)g_wlb)[e] = hi;
    ((__nv_bfloat16*)g_wlb)[L_*2*H_ + e] = lo;
}

// ---------------- FOFE weights per (b,s,w) ----------------
__global__ void k_wts(const int* __restrict__ chars, const float* __restrict__ forget_p){
    int bs = blockIdx.x * 256 + threadIdx.x;
    if (bs >= B_*S_) return;
    const int* cp = chars + bs*W_;
    float f = forget_p[0];
    int c[W_];
#pragma unroll
    for (int w = 0; w < W_; ++w) c[w] = cp[w];
    int cnt = 0;
    float wt[W_];
#pragma unroll
    for (int w = W_-1; w >= 0; --w){
        wt[w] = (c[w] != 0) ? powf(f, (float)cnt) : 0.f;
        cnt += (c[w] != 0);
    }
#pragma unroll
    for (int w = 0; w < W_; ++w) g_wt[bs*W_ + w] = wt[w];
}

// ---------------- sparse xw: dual-g threads, warp-uniform rows ------------
__global__ void __launch_bounds__(256)
k_xws(const int* __restrict__ chars, const int* __restrict__ lengths,
      const float* __restrict__ Wf, const float* __restrict__ Wb,
      const float* __restrict__ bf, const float* __restrict__ bb){
    extern __shared__ char sm[];
    float* Wsm = (float*)(sm + XS_WS);   // [v][66]
    float* Os  = (float*)(sm + XS_OS);   // [b][66]
    int*   Cs  = (int*)  (sm + XS_CS);   // [b][16] (prescaled by 66)
    float* Fs  = (float*)(sm + XS_FS);   // [b][16]
    const int tid = threadIdx.x;
    const int gt = blockIdx.x, t = blockIdx.y, dir = blockIdx.z;
    const int g0 = gt * XT_G;
    const float* Wih = dir ? Wb : Wf;
    const float* bih = dir ? bb : bf;

    for (int i = tid; i < XT_G*V_; i += 256){
        int v = i & 127, gl = i >> 7;
        Wsm[v*66 + gl] = Wih[(g0 + gl)*V_ + v];
    }
    for (int i = tid; i < B_*W_; i += 256){
        int b = i >> 4, w = i & 15;
        int s = t;
        if (dir){ s = lengths[b] - 1 - t; if (s < 0) s = 0; }
        int bs = b*S_ + s;
        Cs[i] = chars[bs*W_ + w] * 66;
        Fs[i] = g_wt[bs*W_ + w];
    }
    __syncthreads();

    const int gp = (tid & 31)*2;         // g-pair
    const int q  = tid >> 5;             // warp-uniform row group (16 rows)
    const float2 bias = *(const float2*)&bih[g0 + gp];
#pragma unroll
    for (int rr = 0; rr < 16; rr += 4){
        const int r0 = q*16 + rr;
        float a[4][2];
#pragma unroll
        for (int j = 0; j < 4; ++j){ a[j][0] = bias.x; a[j][1] = bias.y; }
#pragma unroll
        for (int w0 = 0; w0 < 16; w0 += 4){
#pragma unroll
            for (int j = 0; j < 4; ++j){
                int4   cj = *(const int4*)  (Cs + (r0+j)*16 + w0);   // broadcast
                float4 fj = *(const float4*)(Fs + (r0+j)*16 + w0);   // broadcast
                float2 w;
                w = *(const float2*)&Wsm[cj.x + gp];
                a[j][0] = fmaf(fj.x, w.x, a[j][0]); a[j][1] = fmaf(fj.x, w.y, a[j][1]);
                w = *(const float2*)&Wsm[cj.y + gp];
                a[j][0] = fmaf(fj.y, w.x, a[j][0]); a[j][1] = fmaf(fj.y, w.y, a[j][1]);
                w = *(const float2*)&Wsm[cj.z + gp];
                a[j][0] = fmaf(fj.z, w.x, a[j][0]); a[j][1] = fmaf(fj.z, w.y, a[j][1]);
                w = *(const float2*)&Wsm[cj.w + gp];
                a[j][0] = fmaf(fj.w, w.x, a[j][0]); a[j][1] = fmaf(fj.w, w.y, a[j][1]);
            }
        }
#pragma unroll
        for (int j = 0; j < 4; ++j)
            *(float2*)&Os[(r0+j)*66 + gp] = make_float2(a[j][0], a[j][1]);
    }
    __syncthreads();

    float* dst = g_xw + ((size_t)(dir*S_ + t)*G3_ + g0)*B_;
    for (int i = tid; i < XT_G*B_; i += 256){
        int gl = i >> 7, b = i & 127;
        dst[gl*B_ + b] = Os[b*66 + gl];
    }
}

// ---------------- persistent recurrent kernel (HMMA + gates) ---------------
__global__ void __launch_bounds__(256)
k_step_pers(const int* __restrict__ lengths, const float* __restrict__ bhf,
            const float* __restrict__ bhb){
    extern __shared__ char sm[];
    const uint32_t sb = s2u(sm);
    const int tid  = threadIdx.x;
    const int lane = tid & 31;
    const int wid  = tid >> 5;
    const int wm = wid & 3, wn = wid >> 2;
    const int cu = blockIdx.x, bh = blockIdx.y, dir = blockIdx.z;
    const int grp = dir*2 + bh;

    for (int i = tid; i < 6144; i += 256){
        int p = i / 3072, j = i % 3072;
        int row = j >> 6, seg = j & 63;
        cpa16(sb + OFF_W + p*WPSZ + row*1040 + seg*16,
              &g_wp[p][dir][cu*48 + row][seg*8]);
    }
    asm volatile("cp.async.commit_group;");

    const int bloc = tid & 63, ub = tid >> 6;
    const int bg = bh*64 + bloc;
    const int mylen = lengths[bg];
    const int ubase = cu*16 + ub*4;
    const float* bhv = dir ? bhb : bhf;
    float bR[4], bZ[4], bN[4];
#pragma unroll
    for (int i = 0; i < 4; ++i){
        int u = ubase + i;
        bR[i] = bhv[u]; bZ[i] = bhv[H_ + u]; bN[i] = bhv[2*H_ + u];
    }
    float hreg[4] = {0.f, 0.f, 0.f, 0.f};

    const int ln = lane & 15;
    const uint32_t aoff = (uint32_t)(wm*16 + (lane & 15))*272 + (uint32_t)(lane >> 4)*16;
    // ldsm4 B: lanes 0-7 nt0/k0, 8-15 nt0/k8, 16-23 nt1/k0, 24-31 nt1/k8
    const uint32_t boff4 = (uint32_t)(wn*24 + (lane & 7) + ((lane >> 4) << 3))*1040
                         + (uint32_t)((lane >> 3) & 1)*16;
    const uint32_t boff2 = (uint32_t)(wn*24 + 16 + (ln & 7))*1040 + (uint32_t)(ln >> 3)*16;
    float* Cs = (float*)(sm + OFF_C);

    asm volatile("cp.async.wait_group 0;");
    __syncthreads();

    for (int t = 0; t < S_; ++t){
        const int par = t & 1;

        float xr[4], xz[4], xn[4];
        {
            const float* xwb = g_xw + ((size_t)(dir*S_ + t))*G3_*B_;
#pragma unroll
            for (int i = 0; i < 4; ++i){
                int u = ubase + i;
                xr[i] = xwb[(size_t)u*B_ + bg];
                xz[i] = xwb[(size_t)(H_ + u)*B_ + bg];
                xn[i] = xwb[(size_t)(2*H_ + u)*B_ + bg];
            }
        }

#pragma unroll
        for (int c = 0; c < 2; ++c){
#pragma unroll
            for (int p = 0; p < 2; ++p)
#pragma unroll
                for (int j = 0; j < 4; ++j){
                    int i = tid + j*256;
                    int row = i >> 4, seg = i & 15;
                    cpa16(sb + OFF_A + (c*2 + p)*ASZ + row*272 + seg*16,
                          &g_hbf[par][dir][p][bh*64 + row][c*128 + seg*8]);
                }
            asm volatile("cp.async.commit_group;");
        }

        float acc[3][4] = {};
        for (int c = 0; c < 4; ++c){
            if (c < 3) asm volatile("cp.async.wait_group 1;");
            else       asm volatile("cp.async.wait_group 0;");
            __syncthreads();
            const int buf = c & 1;
            const uint32_t Ah = sb + OFF_A + (buf*2)*ASZ + aoff;
            const uint32_t Al = Ah + ASZ;
            const uint32_t Bq = sb + OFF_W + boff4 + (uint32_t)c*256;
            const uint32_t B2 = sb + OFF_W + boff2 + (uint32_t)c*256;
#pragma unroll
            for (int ks = 0; ks < 8; ++ks){
                uint32_t aH[4], aL[4], bqH[4], bqL[4], b2H[2], b2L[2];
                ldsm4(aH, Ah + ks*32);
                ldsm4(aL, Al + ks*32);
                ldsm4(bqH, Bq + ks*32);
                ldsm4(bqL, Bq + WPSZ + ks*32);
                ldsm2(b2H, B2 + ks*32);
                ldsm2(b2L, B2 + WPSZ + ks*32);
                mma16816(acc[0], aH, bqH);
                mma16816(acc[0], aL, bqH);
                mma16816(acc[0], aH, bqL);
                mma16816(acc[1], aH, bqH + 2);
                mma16816(acc[1], aL, bqH + 2);
                mma16816(acc[1], aH, bqL + 2);
                mma16816(acc[2], aH, b2H);
                mma16816(acc[2], aL, b2H);
                mma16816(acc[2], aH, b2L);
            }
            __syncthreads();
            if (c < 2){
#pragma unroll
                for (int p = 0; p < 2; ++p)
#pragma unroll
                    for (int j = 0; j < 4; ++j){
                        int i = tid + j*256;
                        int row = i >> 4, seg = i & 15;
                        cpa16(sb + OFF_A + (buf*2 + p)*ASZ + row*272 + seg*16,
                              &g_hbf[par][dir][p][bh*64 + row][(c+2)*128 + seg*8]);
                    }
                asm volatile("cp.async.commit_group;");
            }
        }

        {
            const int trow = lane >> 2, tcol = (lane & 3)*2;
#pragma unroll
            for (int nt = 0; nt < 3; ++nt){
                int n = wn*24 + nt*8 + tcol;
                int m = wm*16 + trow;
                Cs[n*68 + m]          = acc[nt][0];
                Cs[(n+1)*68 + m]      = acc[nt][1];
                Cs[n*68 + m + 8]      = acc[nt][2];
                Cs[(n+1)*68 + m + 8]  = acc[nt][3];
            }
        }
        __syncthreads();

        {
            const bool msk = (t < mylen);
            const int par2 = par ^ 1;
            __nv_bfloat16 ohi[4], olo[4];
#pragma unroll
            for (int i = 0; i < 4; ++i){
                const int ul = ub*4 + i;
                float pr = Cs[(ul*3+0)*68 + bloc] + bR[i] + xr[i];
                float pz = Cs[(ul*3+1)*68 + bloc] + bZ[i] + xz[i];
                float pn = Cs[(ul*3+2)*68 + bloc] + bN[i];
                float r = fsig(pr);
                float z = fsig(pz);
                float n = ftanh(xn[i] + r*pn);
                float hnew = (1.f - z)*n + z*hreg[i];
                float gv = msk ? hnew : 0.f;
                if (msk) hreg[i] = hnew;
                ohi[i] = __float2bfloat16(gv);
                olo[i] = __float2bfloat16(gv - __bfloat162float(ohi[i]));
            }
            *(uint2*)&g_gb[0][dir][t][bg][ubase] = *(uint2*)ohi;
            *(uint2*)&g_gb[1][dir][t][bg][ubase] = *(uint2*)olo;
            __nv_bfloat16 hi[4], lo[4];
#pragma unroll
            for (int i = 0; i < 4; ++i){
                hi[i] = __float2bfloat16(hreg[i]);
                lo[i] = __float2bfloat16(hreg[i] - __bfloat162float(hi[i]));
            }
            *(uint2*)&g_hbf[par2][dir][0][bg][ubase] = *(uint2*)hi;
            *(uint2*)&g_hbf[par2][dir][1][bg][ubase] = *(uint2*)lo;
        }

        // quadrant-local barrier: 32 CTAs, release/acquire
        __syncthreads();
        if (tid == 0){
            asm volatile("red.release.gpu.global.add.s32 [%0], 1;"
                         :: "l"(&g_bar4[grp]) : "memory");
            const int target = 32*(t+1);
            int v;
            do {
                asm volatile("ld.global.acquire.gpu.b32 %0, [%1];" : "=r"(v) : "l"(&g_bar4[grp]));
            } while (v < target);
        }
        __syncthreads();
    }
}

// ---------------- final linear via HMMA (3-term split bf16) ----------------
__global__ void __launch_bounds__(256)
k_lin_mma(const int* __restrict__ lengths, const float* __restrict__ blin,
          float* __restrict__ out){
    extern __shared__ char sm[];
    const uint32_t sb = s2u(sm);
    const int tid  = threadIdx.x;
    const int lane = tid & 31;
    const int wid  = tid >> 5;
    const int wm = wid & 3, wn = wid >> 2;       // m 16-tile, n 32-half
    const int r0 = blockIdx.x * 64;

    __shared__ const __nv_bfloat16* pF[2][64];
    __shared__ const __nv_bfloat16* pB[2][64];
    if (tid < 128){
        int p = tid >> 6, row = tid & 63;
        int r = r0 + row;
        int b = r >> 7, s = r & 127;
        pF[p][row] = &g_gb[p][0][s][b][0];
        int len = lengths[b];
        pB[p][row] = (s < len) ? &g_gb[p][1][len-1-s][b][0]
                               : (const __nv_bfloat16*)g_zbuf;
    }
    __syncthreads();

    auto fill = [&](int c, int buf){
#pragma unroll
        for (int p = 0; p < 2; ++p){
            uint32_t Abase = sb + LOFF_A + (buf*2 + p)*LASZ;
#pragma unroll
            for (int j = 0; j < 4; ++j){
                int i = tid + j*256;
                int row = i >> 4, seg = i & 15;
                const __nv_bfloat16* src = (c < 4)
                    ? pF[p][row] + c*128 + seg*8
                    : pB[p][row] + ((pB[p][row] == (const __nv_bfloat16*)g_zbuf) ? seg*8
                                    : (c-4)*128 + seg*8);
                cpa16(Abase + row*272 + seg*16, src);
            }
            uint32_t Bbase = sb + LOFF_B + (buf*2 + p)*LASZ;
#pragma unroll
            for (int j = 0; j < 4; ++j){
                int i = tid + j*256;
                int n = i >> 4, seg = i & 15;
                cpa16(Bbase + n*272 + seg*16, &g_wlb[p][n][c*128 + seg*8]);
            }
        }
        asm volatile("cp.async.commit_group;");
    };

    fill(0, 0);
    fill(1, 1);

    const int ln = lane & 15;
    const uint32_t aoff = (uint32_t)(wm*16 + (lane & 15))*272 + (uint32_t)(lane >> 4)*16;
    const uint32_t boff = (uint32_t)(wn*32 + (ln & 7))*272 + (uint32_t)(ln >> 3)*16;
    float acc[4][4] = {};

    for (int c = 0; c < 8; ++c){
        if (c < 6) asm volatile("cp.async.wait_group 1;");
        else       asm volatile("cp.async.wait_group 0;");
        __syncthreads();
        const int buf = c & 1;
        const uint32_t Ah = sb + LOFF_A + (buf*2)*LASZ + aoff;
        const uint32_t Al = Ah + LASZ;
        const uint32_t Bh = sb + LOFF_B + (buf*2)*LASZ + boff;
        const uint32_t Bl = Bh + LASZ;
#pragma unroll
        for (int ks = 0; ks < 8; ++ks){
            uint32_t aH[4], aL[4];
            ldsm4(aH, Ah + ks*32);
            ldsm4(aL, Al + ks*32);
#pragma unroll
            for (int nt = 0; nt < 4; ++nt){
                uint32_t bH[2], bL[2];
                ldsm2(bH, Bh + (uint32_t)nt*8*272 + (uint32_t)ks*32);
                ldsm2(bL, Bl + (uint32_t)nt*8*272 + (uint32_t)ks*32);
                mma16816(acc[nt], aH, bH);
                mma16816(acc[nt], aL, bH);
                mma16816(acc[nt], aH, bL);
            }
        }
        __syncthreads();
        if (c < 6) fill(c + 2, buf);
    }

    float* Cs = (float*)(sm + LOFF_C);   // [n 64][m 68]
    {
        const int trow = lane >> 2, tcol = (lane & 3)*2;
#pragma unroll
        for (int nt = 0; nt < 4; ++nt){
            int n = wn*32 + nt*8 + tcol;
            int m = wm*16 + trow;
            Cs[n*68 + m]          = acc[nt][0];
            Cs[(n+1)*68 + m]      = acc[nt][1];
            Cs[n*68 + m + 8]      = acc[nt][2];
            Cs[(n+1)*68 + m + 8]  = acc[nt][3];
        }
    }
    __syncthreads();

    {
        const int row = tid & 63, lq = tid >> 6;
        float* dst = out + (size_t)(r0 + row)*L_;
#pragma unroll
        for (int j = 0; j < 4; ++j){
            int l = lq*16 + j*4;
            float4 v;
            v.x = Cs[(l+0)*68 + row] + blin[l+0];
            v.y = Cs[(l+1)*68 + row] + blin[l+1];
            v.z = Cs[(l+2)*68 + row] + blin[l+2];
            v.w = Cs[(l+3)*68 + row] + blin[l+3];
            *(float4*)(dst + l) = v;
        }
    }
}

// ---------------- launch ----------------
extern "C" void kernel_launch(void* const* d_in, const int* in_sizes, int n_in,
                              void* d_out, int out_size) {
    const int*   chars   = (const int*)  d_in[0];
    const int*   lengths = (const int*)  d_in[1];
    const float* forget  = (const float*)d_in[2];
    const float* W_ih_f  = (const float*)d_in[3];
    const float* W_hh_f  = (const float*)d_in[4];
    const float* b_ih_f  = (const float*)d_in[5];
    const float* b_hh_f  = (const float*)d_in[6];
    const float* W_ih_b  = (const float*)d_in[7];
    const float* W_hh_b  = (const float*)d_in[8];
    const float* b_ih_b  = (const float*)d_in[9];
    const float* b_hh_b  = (const float*)d_in[10];
    const float* W_lin   = (const float*)d_in[11];
    const float* b_lin   = (const float*)d_in[12];
    float* out = (float*)d_out;

    cudaFuncSetAttribute(k_step_pers, cudaFuncAttributeMaxDynamicSharedMemorySize, STEP_SMEM);
    cudaFuncSetAttribute(k_xws, cudaFuncAttributeMaxDynamicSharedMemorySize, XS_SMEM);
    cudaFuncSetAttribute(k_lin_mma, cudaFuncAttributeMaxDynamicSharedMemorySize, LIN_SMEM);

    k_zero <<<1024, 256>>>();
    k_prep <<<(2*G3_*H_ + 255)/256, 256>>>(W_hh_f, W_hh_b);
    k_prepL<<<(L_*2*H_ + 255)/256, 256>>>(W_lin);
    k_wts  <<<(B_*S_ + 255)/256, 256>>>(chars, forget);
    k_xws  <<<dim3(G3_/XT_G, S_, 2), 256, XS_SMEM>>>(chars, lengths, W_ih_f, W_ih_b, b_ih_f, b_ih_b);
    k_step_pers<<<dim3(32, 2, 2), 256, STEP_SMEM>>>(lengths, b_hh_f, b_hh_b);
    k_lin_mma<<<(S_*B_)/64, 256, LIN_SMEM>>>(lengths, b_lin, out);
}

// round 17
// speedup vs baseline: 1.4620x; 1.4620x over previous
#include <cuda_runtime.h>
#include <cuda_bf16.h>
#include <math.h>
#include <stdint.h>

#define B_  128
#define S_  128
#define W_  16
#define V_  128
#define H_  512
#define G3_ 1536
#define L_  64

// k_step smem layout
#define WPSZ  49920                    // 48 rows x 1040B per precision
#define OFF_W 0                        // 2 prec -> 99840
#define ASZ   17408                    // 64 rows x 272B
#define OFF_A 99840                    // [buf][prec] x 17408 -> 69632
#define OFF_C 169472                   // 48 x 68 fp32 = 13056
#define STEP_SMEM 182528

// k_xws smem layout (g-tile 64, dual-g threads)
#define XT_G  64
#define XS_WS 0                        // 128 v x 66 fp32 = 33792
#define XS_OS 33792                    // 128 b x 66 fp32 = 33792
#define XS_CS 67584                    // 128 b x 16 int  = 8192
#define XS_FS 75776                    // 128 b x 16 fp32 = 8192
#define XS_SMEM 83968

// k_lin_mma smem layout
#define LASZ  17408                    // 64 rows x 272B
#define LOFF_A 0                       // [buf2][prec2] -> 69632
#define LOFF_B 69632                   // [buf2][prec2] -> 69632
#define LOFF_C 139264                  // 64 x 68 fp32 = 17408
#define LIN_SMEM 156672

// ---------------- scratch (device globals; no allocation) ----------------
__device__ float g_wt [B_*S_*W_];
__device__ float g_xw [(size_t)2*S_*G3_*B_];          // [dir][t][g][b] incl b_ih
__device__ __nv_bfloat16 g_hbf[2][2][2][B_][H_];      // [parity][dir][prec][b][k]
__device__ __nv_bfloat16 g_wp [2][2][G3_][H_];        // [prec][dir][perm row][k]
__device__ __nv_bfloat16 g_gb [2][2][S_][B_][H_];     // [prec][dir][t][b][u] masked out
__device__ __nv_bfloat16 g_wlb[2][L_][2*H_];          // [prec][l][k] W_lin split
__device__ float g_zbuf[64];                          // stays zero (never written)
__device__ int   g_bar4[4];

// ---------------- helpers ----------------
__device__ __forceinline__ uint32_t s2u(const void* p){
    uint32_t a;
    asm("{ .reg .u64 t; cvta.to.shared.u64 t, %1; cvt.u32.u64 %0, t; }" : "=r"(a) : "l"(p));
    return a;
}
__device__ __forceinline__ void ldsm4(uint32_t* r, uint32_t a){
    asm volatile("ldmatrix.sync.aligned.m8n8.x4.shared.b16 {%0,%1,%2,%3}, [%4];"
        : "=r"(r[0]), "=r"(r[1]), "=r"(r[2]), "=r"(r[3]) : "r"(a));
}
__device__ __forceinline__ void ldsm2(uint32_t* r, uint32_t a){
    asm volatile("ldmatrix.sync.aligned.m8n8.x2.shared.b16 {%0,%1}, [%2];"
        : "=r"(r[0]), "=r"(r[1]) : "r"(a));
}
__device__ __forceinline__ void mma16816(float* c, const uint32_t* a, const uint32_t* b){
    asm volatile("mma.sync.aligned.m16n8k16.row.col.f32.bf16.bf16.f32 "
        "{%0,%1,%2,%3}, {%4,%5,%6,%7}, {%8,%9}, {%0,%1,%2,%3};"
        : "+f"(c[0]), "+f"(c[1]), "+f"(c[2]), "+f"(c[3])
        : "r"(a[0]), "r"(a[1]), "r"(a[2]), "r"(a[3]), "r"(b[0]), "r"(b[1]));
}
__device__ __forceinline__ void cpa16(uint32_t dst, const void* src){
    asm volatile("cp.async.cg.shared.global [%0], [%1], 16;" :: "r"(dst), "l"(src));
}
__device__ __forceinline__ float fsig(float x){
    return __fdividef(1.f, 1.f + __expf(-x));
}
__device__ __forceinline__ float ftanh(float x){
    float e = __expf(2.f*fabsf(x));
    return copysignf(1.f - __fdividef(2.f, e + 1.f), x);
}

// ---------------- init (re-run every replay) ----------------
__global__ void k_zero(){
    int i = blockIdx.x * 256 + threadIdx.x;
    if (i < 4*B_*H_) ((uint32_t*)g_hbf)[i] = 0u;
    if (i < 4) g_bar4[i] = 0;
}

// ---------------- permute + split W_hh into bf16 hi/lo --------------------
__global__ void k_prep(const float* __restrict__ Wf, const float* __restrict__ Wb){
    int e = blockIdx.x * 256 + threadIdx.x;
    if (e >= 2*G3_*H_) return;
    int dir = e / (G3_*H_);
    int rem = e - dir*(G3_*H_);
    int ro  = rem / H_;
    int k   = rem % H_;
    int u = ro / 3, g = ro % 3;
    float w = (dir ? Wb : Wf)[(g*H_ + u)*H_ + k];
    __nv_bfloat16 hi = __float2bfloat16(w);
    __nv_bfloat16 lo = __float2bfloat16(w - __bfloat162float(hi));
    g_wp[0][dir][ro][k] = hi;
    g_wp[1][dir][ro][k] = lo;
}

// ---------------- split W_lin into bf16 hi/lo ----------------
__global__ void k_prepL(const float* __restrict__ Wlin){
    int e = blockIdx.x * 256 + threadIdx.x;
    if (e >= L_*2*H_) return;
    float w = Wlin[e];
    __nv_bfloat16 hi = __float2bfloat16(w);
    __nv_bfloat16 lo = __float2bfloat16(w - __bfloat162float(hi));
    ((__nv_bfloat16*)g_wlb)[e] = hi;
    ((__nv_bfloat16*)g_wlb)[L_*2*H_ + e] = lo;
}

// ---------------- FOFE weights per (b,s,w) ----------------
__global__ void k_wts(const int* __restrict__ chars, const float* __restrict__ forget_p){
    int bs = blockIdx.x * 256 + threadIdx.x;
    if (bs >= B_*S_) return;
    const int* cp = chars + bs*W_;
    float f = forget_p[0];
    int c[W_];
#pragma unroll
    for (int w = 0; w < W_; ++w) c[w] = cp[w];
    int cnt = 0;
    float wt[W_];
#pragma unroll
    for (int w = W_-1; w >= 0; --w){
        wt[w] = (c[w] != 0) ? powf(f, (float)cnt) : 0.f;
        cnt += (c[w] != 0);
    }
#pragma unroll
    for (int w = 0; w < W_; ++w) g_wt[bs*W_ + w] = wt[w];
}

// ---------------- sparse xw: dual-g threads, warp-uniform rows ------------
__global__ void __launch_bounds__(256)
k_xws(const int* __restrict__ chars, const int* __restrict__ lengths,
      const float* __restrict__ Wf, const float* __restrict__ Wb,
      const float* __restrict__ bf, const float* __restrict__ bb){
    extern __shared__ char sm[];
    float* Wsm = (float*)(sm + XS_WS);   // [v][66]
    float* Os  = (float*)(sm + XS_OS);   // [b][66]
    int*   Cs  = (int*)  (sm + XS_CS);   // [b][16] (prescaled by 66)
    float* Fs  = (float*)(sm + XS_FS);   // [b][16]
    const int tid = threadIdx.x;
    const int gt = blockIdx.x, t = blockIdx.y, dir = blockIdx.z;
    const int g0 = gt * XT_G;
    const float* Wih = dir ? Wb : Wf;
    const float* bih = dir ? bb : bf;

    for (int i = tid; i < XT_G*V_; i += 256){
        int v = i & 127, gl = i >> 7;
        Wsm[v*66 + gl] = Wih[(g0 + gl)*V_ + v];
    }
    for (int i = tid; i < B_*W_; i += 256){
        int b = i >> 4, w = i & 15;
        int s = t;
        if (dir){ s = lengths[b] - 1 - t; if (s < 0) s = 0; }
        int bs = b*S_ + s;
        Cs[i] = chars[bs*W_ + w] * 66;
        Fs[i] = g_wt[bs*W_ + w];
    }
    __syncthreads();

    const int gp = (tid & 31)*2;         // g-pair
    const int q  = tid >> 5;             // warp-uniform row group (16 rows)
    const float2 bias = *(const float2*)&bih[g0 + gp];
#pragma unroll
    for (int rr = 0; rr < 16; rr += 4){
        const int r0 = q*16 + rr;
        float a[4][2];
#pragma unroll
        for (int j = 0; j < 4; ++j){ a[j][0] = bias.x; a[j][1] = bias.y; }
#pragma unroll
        for (int w0 = 0; w0 < 16; w0 += 4){
#pragma unroll
            for (int j = 0; j < 4; ++j){
                int4   cj = *(const int4*)  (Cs + (r0+j)*16 + w0);   // broadcast
                float4 fj = *(const float4*)(Fs + (r0+j)*16 + w0);   // broadcast
                float2 w;
                w = *(const float2*)&Wsm[cj.x + gp];
                a[j][0] = fmaf(fj.x, w.x, a[j][0]); a[j][1] = fmaf(fj.x, w.y, a[j][1]);
                w = *(const float2*)&Wsm[cj.y + gp];
                a[j][0] = fmaf(fj.y, w.x, a[j][0]); a[j][1] = fmaf(fj.y, w.y, a[j][1]);
                w = *(const float2*)&Wsm[cj.z + gp];
                a[j][0] = fmaf(fj.z, w.x, a[j][0]); a[j][1] = fmaf(fj.z, w.y, a[j][1]);
                w = *(const float2*)&Wsm[cj.w + gp];
                a[j][0] = fmaf(fj.w, w.x, a[j][0]); a[j][1] = fmaf(fj.w, w.y, a[j][1]);
            }
        }
#pragma unroll
        for (int j = 0; j < 4; ++j)
            *(float2*)&Os[(r0+j)*66 + gp] = make_float2(a[j][0], a[j][1]);
    }
    __syncthreads();

    float* dst = g_xw + ((size_t)(dir*S_ + t)*G3_ + g0)*B_;
    for (int i = tid; i < XT_G*B_; i += 256){
        int gl = i >> 7, b = i & 127;
        dst[gl*B_ + b] = Os[b*66 + gl];
    }
}

// ---------------- persistent recurrent kernel (HMMA + gates) ---------------
__global__ void __launch_bounds__(256)
k_step_pers(const int* __restrict__ lengths, const float* __restrict__ bhf,
            const float* __restrict__ bhb){
    extern __shared__ char sm[];
    const uint32_t sb = s2u(sm);
    const int tid  = threadIdx.x;
    const int lane = tid & 31;
    const int wid  = tid >> 5;
    const int wm = wid & 3, wn = wid >> 2;
    const int cu = blockIdx.x, bh = blockIdx.y, dir = blockIdx.z;
    const int grp = dir*2 + bh;

    for (int i = tid; i < 6144; i += 256){
        int p = i / 3072, j = i % 3072;
        int row = j >> 6, seg = j & 63;
        cpa16(sb + OFF_W + p*WPSZ + row*1040 + seg*16,
              &g_wp[p][dir][cu*48 + row][seg*8]);
    }
    asm volatile("cp.async.commit_group;");

    const int bloc = tid & 63, ub = tid >> 6;
    const int bg = bh*64 + bloc;
    const int mylen = lengths[bg];
    const int ubase = cu*16 + ub*4;
    const float* bhv = dir ? bhb : bhf;
    float bR[4], bZ[4], bN[4];
#pragma unroll
    for (int i = 0; i < 4; ++i){
        int u = ubase + i;
        bR[i] = bhv[u]; bZ[i] = bhv[H_ + u]; bN[i] = bhv[2*H_ + u];
    }
    float hreg[4] = {0.f, 0.f, 0.f, 0.f};

    const int ln = lane & 15;
    const uint32_t aoff = (uint32_t)(wm*16 + (lane & 15))*272 + (uint32_t)(lane >> 4)*16;
    // ldsm4 B: lanes 0-7 nt0/k0, 8-15 nt0/k8, 16-23 nt1/k0, 24-31 nt1/k8
    const uint32_t boff4 = (uint32_t)(wn*24 + (lane & 7) + ((lane >> 4) << 3))*1040
                         + (uint32_t)((lane >> 3) & 1)*16;
    const uint32_t boff2 = (uint32_t)(wn*24 + 16 + (ln & 7))*1040 + (uint32_t)(ln >> 3)*16;
    float* Cs = (float*)(sm + OFF_C);

    asm volatile("cp.async.wait_group 0;");
    __syncthreads();

    // xw prefetch for step 0 (consumed in epilogue; refreshed pre-barrier)
    float xr[4], xz[4], xn[4];
    {
        const float* xwb = g_xw + ((size_t)(dir*S_ + 0))*G3_*B_;
#pragma unroll
        for (int i = 0; i < 4; ++i){
            int u = ubase + i;
            xr[i] = xwb[(size_t)u*B_ + bg];
            xz[i] = xwb[(size_t)(H_ + u)*B_ + bg];
            xn[i] = xwb[(size_t)(2*H_ + u)*B_ + bg];
        }
    }

    for (int t = 0; t < S_; ++t){
        const int par = t & 1;

#pragma unroll
        for (int c = 0; c < 2; ++c){
#pragma unroll
            for (int p = 0; p < 2; ++p)
#pragma unroll
                for (int j = 0; j < 4; ++j){
                    int i = tid + j*256;
                    int row = i >> 4, seg = i & 15;
                    cpa16(sb + OFF_A + (c*2 + p)*ASZ + row*272 + seg*16,
                          &g_hbf[par][dir][p][bh*64 + row][c*128 + seg*8]);
                }
            asm volatile("cp.async.commit_group;");
        }

        float acc[3][4] = {};
        for (int c = 0; c < 4; ++c){
            if (c < 3) asm volatile("cp.async.wait_group 1;");
            else       asm volatile("cp.async.wait_group 0;");
            __syncthreads();
            const int buf = c & 1;
            const uint32_t Ah = sb + OFF_A + (buf*2)*ASZ + aoff;
            const uint32_t Al = Ah + ASZ;
            const uint32_t Bq = sb + OFF_W + boff4 + (uint32_t)c*256;
            const uint32_t B2 = sb + OFF_W + boff2 + (uint32_t)c*256;
#pragma unroll
            for (int ks = 0; ks < 8; ++ks){
                uint32_t aH[4], aL[4], bqH[4], bqL[4], b2H[2], b2L[2];
                ldsm4(aH, Ah + ks*32);
                ldsm4(aL, Al + ks*32);
                ldsm4(bqH, Bq + ks*32);
                ldsm4(bqL, Bq + WPSZ + ks*32);
                ldsm2(b2H, B2 + ks*32);
                ldsm2(b2L, B2 + WPSZ + ks*32);
                mma16816(acc[0], aH, bqH);
                mma16816(acc[0], aL, bqH);
                mma16816(acc[0], aH, bqL);
                mma16816(acc[1], aH, bqH + 2);
                mma16816(acc[1], aL, bqH + 2);
                mma16816(acc[1], aH, bqL + 2);
                mma16816(acc[2], aH, b2H);
                mma16816(acc[2], aL, b2H);
                mma16816(acc[2], aH, b2L);
            }
            __syncthreads();
            if (c < 2){
#pragma unroll
                for (int p = 0; p < 2; ++p)
#pragma unroll
                    for (int j = 0; j < 4; ++j){
                        int i = tid + j*256;
                        int row = i >> 4, seg = i & 15;
                        cpa16(sb + OFF_A + (buf*2 + p)*ASZ + row*272 + seg*16,
                              &g_hbf[par][dir][p][bh*64 + row][(c+2)*128 + seg*8]);
                    }
                asm volatile("cp.async.commit_group;");
            }
        }

        {
            const int trow = lane >> 2, tcol = (lane & 3)*2;
#pragma unroll
            for (int nt = 0; nt < 3; ++nt){
                int n = wn*24 + nt*8 + tcol;
                int m = wm*16 + trow;
                Cs[n*68 + m]          = acc[nt][0];
                Cs[(n+1)*68 + m]      = acc[nt][1];
                Cs[n*68 + m + 8]      = acc[nt][2];
                Cs[(n+1)*68 + m + 8]  = acc[nt][3];
            }
        }
        __syncthreads();

        {
            const bool msk = (t < mylen);
            const int par2 = par ^ 1;
            __nv_bfloat16 ohi[4], olo[4];
#pragma unroll
            for (int i = 0; i < 4; ++i){
                const int ul = ub*4 + i;
                float pr = Cs[(ul*3+0)*68 + bloc] + bR[i] + xr[i];
                float pz = Cs[(ul*3+1)*68 + bloc] + bZ[i] + xz[i];
                float pn = Cs[(ul*3+2)*68 + bloc] + bN[i];
                float r = fsig(pr);
                float z = fsig(pz);
                float n = ftanh(xn[i] + r*pn);
                float hnew = (1.f - z)*n + z*hreg[i];
                float gv = msk ? hnew : 0.f;
                if (msk) hreg[i] = hnew;
                ohi[i] = __float2bfloat16(gv);
                olo[i] = __float2bfloat16(gv - __bfloat162float(ohi[i]));
            }
            *(uint2*)&g_gb[0][dir][t][bg][ubase] = *(uint2*)ohi;
            *(uint2*)&g_gb[1][dir][t][bg][ubase] = *(uint2*)olo;
            __nv_bfloat16 hi[4], lo[4];
#pragma unroll
            for (int i = 0; i < 4; ++i){
                hi[i] = __float2bfloat16(hreg[i]);
                lo[i] = __float2bfloat16(hreg[i] - __bfloat162float(hi[i]));
            }
            *(uint2*)&g_hbf[par2][dir][0][bg][ubase] = *(uint2*)hi;
            *(uint2*)&g_hbf[par2][dir][1][bg][ubase] = *(uint2*)lo;
        }

        // prefetch next step's xw BEFORE the barrier (independent of h writes)
        if (t + 1 < S_){
            const float* xwb = g_xw + ((size_t)(dir*S_ + (t+1)))*G3_*B_;
#pragma unroll
            for (int i = 0; i < 4; ++i){
                int u = ubase + i;
                xr[i] = xwb[(size_t)u*B_ + bg];
                xz[i] = xwb[(size_t)(H_ + u)*B_ + bg];
                xn[i] = xwb[(size_t)(2*H_ + u)*B_ + bg];
            }
        }

        // quadrant-local barrier: 32 CTAs, release/acquire
        __syncthreads();
        if (tid == 0){
            asm volatile("red.release.gpu.global.add.s32 [%0], 1;"
                         :: "l"(&g_bar4[grp]) : "memory");
            const int target = 32*(t+1);
            int v;
            do {
                asm volatile("ld.global.acquire.gpu.b32 %0, [%1];" : "=r"(v) : "l"(&g_bar4[grp]));
            } while (v < target);
        }
        __syncthreads();
    }
}

// ---------------- final linear via HMMA (3-term split bf16) ----------------
__global__ void __launch_bounds__(256)
k_lin_mma(const int* __restrict__ lengths, const float* __restrict__ blin,
          float* __restrict__ out){
    extern __shared__ char sm[];
    const uint32_t sb = s2u(sm);
    const int tid  = threadIdx.x;
    const int lane = tid & 31;
    const int wid  = tid >> 5;
    const int wm = wid & 3, wn = wid >> 2;       // m 16-tile, n 32-half
    const int r0 = blockIdx.x * 64;

    __shared__ const __nv_bfloat16* pF[2][64];
    __shared__ const __nv_bfloat16* pB[2][64];
    if (tid < 128){
        int p = tid >> 6, row = tid & 63;
        int r = r0 + row;
        int b = r >> 7, s = r & 127;
        pF[p][row] = &g_gb[p][0][s][b][0];
        int len = lengths[b];
        pB[p][row] = (s < len) ? &g_gb[p][1][len-1-s][b][0]
                               : (const __nv_bfloat16*)g_zbuf;
    }
    __syncthreads();

    auto fill = [&](int c, int buf){
#pragma unroll
        for (int p = 0; p < 2; ++p){
            uint32_t Abase = sb + LOFF_A + (buf*2 + p)*LASZ;
#pragma unroll
            for (int j = 0; j < 4; ++j){
                int i = tid + j*256;
                int row = i >> 4, seg = i & 15;
                const __nv_bfloat16* src = (c < 4)
                    ? pF[p][row] + c*128 + seg*8
                    : pB[p][row] + ((pB[p][row] == (const __nv_bfloat16*)g_zbuf) ? seg*8
                                    : (c-4)*128 + seg*8);
                cpa16(Abase + row*272 + seg*16, src);
            }
            uint32_t Bbase = sb + LOFF_B + (buf*2 + p)*LASZ;
#pragma unroll
            for (int j = 0; j < 4; ++j){
                int i = tid + j*256;
                int n = i >> 4, seg = i & 15;
                cpa16(Bbase + n*272 + seg*16, &g_wlb[p][n][c*128 + seg*8]);
            }
        }
        asm volatile("cp.async.commit_group;");
    };

    fill(0, 0);
    fill(1, 1);

    const int ln = lane & 15;
    const uint32_t aoff = (uint32_t)(wm*16 + (lane & 15))*272 + (uint32_t)(lane >> 4)*16;
    const uint32_t boff = (uint32_t)(wn*32 + (ln & 7))*272 + (uint32_t)(ln >> 3)*16;
    float acc[4][4] = {};

    for (int c = 0; c < 8; ++c){
        if (c < 6) asm volatile("cp.async.wait_group 1;");
        else       asm volatile("cp.async.wait_group 0;");
        __syncthreads();
        const int buf = c & 1;
        const uint32_t Ah = sb + LOFF_A + (buf*2)*LASZ + aoff;
        const uint32_t Al = Ah + LASZ;
        const uint32_t Bh = sb + LOFF_B + (buf*2)*LASZ + boff;
        const uint32_t Bl = Bh + LASZ;
#pragma unroll
        for (int ks = 0; ks < 8; ++ks){
            uint32_t aH[4], aL[4];
            ldsm4(aH, Ah + ks*32);
            ldsm4(aL, Al + ks*32);
#pragma unroll
            for (int nt = 0; nt < 4; ++nt){
                uint32_t bH[2], bL[2];
                ldsm2(bH, Bh + (uint32_t)nt*8*272 + (uint32_t)ks*32);
                ldsm2(bL, Bl + (uint32_t)nt*8*272 + (uint32_t)ks*32);
                mma16816(acc[nt], aH, bH);
                mma16816(acc[nt], aL, bH);
                mma16816(acc[nt], aH, bL);
            }
        }
        __syncthreads();
        if (c < 6) fill(c + 2, buf);
    }

    float* Cs = (float*)(sm + LOFF_C);   // [n 64][m 68]
    {
        const int trow = lane >> 2, tcol = (lane & 3)*2;
#pragma unroll
        for (int nt = 0; nt < 4; ++nt){
            int n = wn*32 + nt*8 + tcol;
            int m = wm*16 + trow;
            Cs[n*68 + m]          = acc[nt][0];
            Cs[(n+1)*68 + m]      = acc[nt][1];
            Cs[n*68 + m + 8]      = acc[nt][2];
            Cs[(n+1)*68 + m + 8]  = acc[nt][3];
        }
    }
    __syncthreads();

    {
        const int row = tid & 63, lq = tid >> 6;
        float* dst = out + (size_t)(r0 + row)*L_;
#pragma unroll
        for (int j = 0; j < 4; ++j){
            int l = lq*16 + j*4;
            float4 v;
            v.x = Cs[(l+0)*68 + row] + blin[l+0];
            v.y = Cs[(l+1)*68 + row] + blin[l+1];
            v.z = Cs[(l+2)*68 + row] + blin[l+2];
            v.w = Cs[(l+3)*68 + row] + blin[l+3];
            *(float4*)(dst + l) = v;
        }
    }
}

// ---------------- launch ----------------
extern "C" void kernel_launch(void* const* d_in, const int* in_sizes, int n_in,
                              void* d_out, int out_size) {
    const int*   chars   = (const int*)  d_in[0];
    const int*   lengths = (const int*)  d_in[1];
    const float* forget  = (const float*)d_in[2];
    const float* W_ih_f  = (const float*)d_in[3];
    const float* W_hh_f  = (const float*)d_in[4];
    const float* b_ih_f  = (const float*)d_in[5];
    const float* b_hh_f  = (const float*)d_in[6];
    const float* W_ih_b  = (const float*)d_in[7];
    const float* W_hh_b  = (const float*)d_in[8];
    const float* b_ih_b  = (const float*)d_in[9];
    const float* b_hh_b  = (const float*)d_in[10];
    const float* W_lin   = (const float*)d_in[11];
    const float* b_lin   = (const float*)d_in[12];
    float* out = (float*)d_out;

    cudaFuncSetAttribute(k_step_pers, cudaFuncAttributeMaxDynamicSharedMemorySize, STEP_SMEM);
    cudaFuncSetAttribute(k_xws, cudaFuncAttributeMaxDynamicSharedMemorySize, XS_SMEM);
    cudaFuncSetAttribute(k_lin_mma, cudaFuncAttributeMaxDynamicSharedMemorySize, LIN_SMEM);

    k_zero <<<1024, 256>>>();
    k_prep <<<(2*G3_*H_ + 255)/256, 256>>>(W_hh_f, W_hh_b);
    k_prepL<<<(L_*2*H_ + 255)/256, 256>>>(W_lin);
    k_wts  <<<(B_*S_ + 255)/256, 256>>>(chars, forget);
    k_xws  <<<dim3(G3_/XT_G, S_, 2), 256, XS_SMEM>>>(chars, lengths, W_ih_f, W_ih_b, b_ih_f, b_ih_b);
    k_step_pers<<<dim3(32, 2, 2), 256, STEP_SMEM>>>(lengths, b_hh_f, b_hh_b);
    k_lin_mma<<<(S_*B_)/64, 256, LIN_SMEM>>>(lengths, b_lin, out);
}